// round 16
// baseline (speedup 1.0000x reference)
#include <cuda_runtime.h>
#include <cuda_fp16.h>
#include <cstdint>

#define NNODES 50000
#define NEDGES 1600000
#define NF     128
#define NG     50
#define CUTOFF_R 5.0f
#define PI_F 3.14159265358979323846f

#define ETILE 64
#define NTILES (NEDGES / ETILE)   // 25000 exact

// ---------------- device scratch ----------------
__device__ float g_hv [NNODES * NF];
__device__ float g_agg[NNODES * NF];
__device__ float g_tmp[NNODES * NF];

// ---------------- helpers ----------------
__device__ __forceinline__ uint32_t smem_u32(const void* p) {
    uint32_t a;
    asm("{ .reg .u64 t; cvta.to.shared.u64 t, %1; cvt.u32.u64 %0, t; }"
        : "=r"(a) : "l"(p));
    return a;
}
__device__ __forceinline__ float swishf(float x) {
    return x * (1.0f / (1.0f + __expf(-x)));
}
__device__ __forceinline__ uint16_t f16_hi(float v) {
    __half h = __float2half_rn(v);
    return __half_raw(h).x;
}
__device__ __forceinline__ uint16_t f16_lo(float v) {
    __half h = __float2half_rn(v);
    float r = v - __half2float(h);
    __half l = __float2half_rn(r);
    return __half_raw(l).x;
}
__device__ __forceinline__ uint32_t pack_h2(float x, float y) {
    __half2 h = __floats2half2_rn(x, y);
    return *reinterpret_cast<uint32_t*>(&h);
}

__device__ __forceinline__ void ldsm4(uint32_t* r, uint32_t a) {
    asm volatile("ldmatrix.sync.aligned.m8n8.x4.shared.b16 {%0,%1,%2,%3}, [%4];"
                 : "=r"(r[0]), "=r"(r[1]), "=r"(r[2]), "=r"(r[3]) : "r"(a));
}
__device__ __forceinline__ void mma16816(float* c, const uint32_t* a, const uint32_t* b) {
    asm volatile(
        "mma.sync.aligned.m16n8k16.row.col.f32.f16.f16.f32 "
        "{%0,%1,%2,%3}, {%4,%5,%6,%7}, {%8,%9}, {%0,%1,%2,%3};"
        : "+f"(c[0]), "+f"(c[1]), "+f"(c[2]), "+f"(c[3])
        : "r"(a[0]), "r"(a[1]), "r"(a[2]), "r"(a[3]), "r"(b[0]), "r"(b[1]));
}
__device__ __forceinline__ void red4(float* p, float x, float y, float z, float w) {
    asm volatile("red.global.add.v4.f32 [%0], {%1,%2,%3,%4};"
                 :: "l"(p), "f"(x), "f"(y), "f"(z), "f"(w) : "memory");
}
__device__ __forceinline__ void cpasync16(uint32_t s, const void* g) {
    asm volatile("cp.async.cg.shared.global [%0], [%1], 16;" :: "r"(s), "l"(g));
}
#define CP_COMMIT() asm volatile("cp.async.commit_group;" ::: "memory")
#define CP_WAIT0()  asm volatile("cp.async.wait_group 0;" ::: "memory")
#define BAR_SYNC(id, cnt) \
    asm volatile("bar.sync %0, %1;" :: "r"(id), "r"(cnt) : "memory")
#define BAR_ARRIVE(id, cnt) \
    asm volatile("bar.arrive %0, %1;" :: "r"(id), "r"(cnt) : "memory")

// ---------------- zero agg + pad (keeps edge_kernel in ncu slot 3) --------
__global__ void zero_agg_kernel() {
    float4* p = reinterpret_cast<float4*>(g_agg);
    int n4 = NNODES * NF / 4;
    for (int i = blockIdx.x * blockDim.x + threadIdx.x; i < n4;
         i += gridDim.x * blockDim.x)
        p[i] = make_float4(0.f, 0.f, 0.f, 0.f);
}
__global__ void pad_kernel() {
    if (blockIdx.x == 0 && threadIdx.x == 0) g_tmp[0] = 0.0f;
}

// ---------------- HMMA node GEMM (working, from R12) ----------------
template <bool SWISH, bool HAS_BIAS>
__device__ __forceinline__ void gemm_hmma(const float* __restrict__ in,
                                          const float* __restrict__ W,
                                          const float* __restrict__ bias,
                                          float* __restrict__ out, int nrows) {
    __shared__ __align__(16) char nsm[34816];
    const int tid  = threadIdx.x;
    const int wid  = tid >> 5;
    const int lane = tid & 31;
    const int f0   = wid * 16;
    const int grp  = lane >> 2;
    const int qid  = lane & 3;
    const int f_r  = f0 + grp;
    const int ec   = qid * 2;
    const int rr   = lane & 15;
    const int cc   = (lane >> 4) * 8;
    const int brow = (lane & 7) + ((lane >> 4) << 3);
    const int bko  = ((lane >> 3) & 1) * 16;
    const uint32_t loff = (uint32_t)brow * 272 + bko;
    const uint32_t sN = smem_u32(nsm);
    const int G = gridDim.x;

    uint32_t awh[32], awl[32];
    for (int idx = tid; idx < 128 * 128; idx += 256) {
        int j = idx & 127, k = idx >> 7;
        *reinterpret_cast<uint16_t*>(nsm + j * 272 + k * 2) = f16_hi(W[k * 128 + j]);
    }
    __syncthreads();
#pragma unroll
    for (int kc = 0; kc < 8; kc++)
        ldsm4(&awh[kc * 4], sN + (f0 + rr) * 272 + (kc * 16 + cc) * 2);
    __syncthreads();
    for (int idx = tid; idx < 128 * 128; idx += 256) {
        int j = idx & 127, k = idx >> 7;
        *reinterpret_cast<uint16_t*>(nsm + j * 272 + k * 2) = f16_lo(W[k * 128 + j]);
    }
    __syncthreads();
#pragma unroll
    for (int kc = 0; kc < 8; kc++)
        ldsm4(&awl[kc * 4], sN + (f0 + rr) * 272 + (kc * 16 + cc) * 2);
    __syncthreads();

    const float ba  = HAS_BIAS ? bias[f_r] : 0.0f;
    const float bb_ = HAS_BIAS ? bias[f_r + 8] : 0.0f;

    const int NT = (nrows + 63) >> 6;
    for (int tile = blockIdx.x; tile < NT; tile += G) {
        for (int idx = tid; idx < 4096; idx += 256) {
            int r = idx >> 6, q = idx & 63;
            int rg = tile * 64 + r;
            int rc = rg < nrows ? rg : 0;
            float2 v = *reinterpret_cast<const float2*>(in + (size_t)rc * 128 + q * 2);
            *reinterpret_cast<uint32_t*>(nsm + r * 272 + q * 4) = pack_h2(v.x, v.y);
        }
        __syncthreads();

#pragma unroll
        for (int np = 0; np < 4; np++) {
            float c0h[4] = {0,0,0,0}, c0l[4] = {0,0,0,0};
            float c1h[4] = {0,0,0,0}, c1l[4] = {0,0,0,0};
#pragma unroll
            for (int kc = 0; kc < 8; kc++) {
                uint32_t bb[4];
                ldsm4(bb, sN + np * (16 * 272) + kc * 32 + loff);
                mma16816(c0h, &awh[kc * 4], &bb[0]);
                mma16816(c0l, &awl[kc * 4], &bb[0]);
                mma16816(c1h, &awh[kc * 4], &bb[2]);
                mma16816(c1l, &awl[kc * 4], &bb[2]);
            }
            int ra = tile * 64 + np * 16 + ec;
            int rb = ra + 8;
            float v;
            if (ra < nrows) {
                v = c0h[0] + c0l[0] + ba; if (SWISH) v = swishf(v);
                out[(size_t)ra * 128 + f_r] = v;
                v = c0h[2] + c0l[2] + bb_; if (SWISH) v = swishf(v);
                out[(size_t)ra * 128 + f_r + 8] = v;
            }
            if (ra + 1 < nrows) {
                v = c0h[1] + c0l[1] + ba; if (SWISH) v = swishf(v);
                out[(size_t)(ra + 1) * 128 + f_r] = v;
                v = c0h[3] + c0l[3] + bb_; if (SWISH) v = swishf(v);
                out[(size_t)(ra + 1) * 128 + f_r + 8] = v;
            }
            if (rb < nrows) {
                v = c1h[0] + c1l[0] + ba; if (SWISH) v = swishf(v);
                out[(size_t)rb * 128 + f_r] = v;
                v = c1h[2] + c1l[2] + bb_; if (SWISH) v = swishf(v);
                out[(size_t)rb * 128 + f_r + 8] = v;
            }
            if (rb + 1 < nrows) {
                v = c1h[1] + c1l[1] + ba; if (SWISH) v = swishf(v);
                out[(size_t)(rb + 1) * 128 + f_r] = v;
                v = c1h[3] + c1l[3] + bb_; if (SWISH) v = swishf(v);
                out[(size_t)(rb + 1) * 128 + f_r + 8] = v;
            }
        }
        __syncthreads();
    }
}

__global__ void __launch_bounds__(256, 2) k_hv(const float* __restrict__ feat,
                                               const float* __restrict__ W_in2f) {
    gemm_hmma<false, false>(feat, W_in2f, nullptr, g_hv, NNODES);
}
__global__ void __launch_bounds__(256, 2) k_m1(const float* __restrict__ Wm1,
                                               const float* __restrict__ bm1) {
    gemm_hmma<true, true>(g_agg, Wm1, bm1, g_tmp, NNODES);
}
__global__ void __launch_bounds__(256, 2) k_m2(const float* __restrict__ Wm2,
                                               const float* __restrict__ bm2,
                                               float* __restrict__ out) {
    gemm_hmma<false, true>(g_tmp, Wm2, bm2, out, NNODES);
}

// ---------------- warp-specialized HMMA edge kernel + hv cp.async ----------
// producers (warps 0-3, 32f each): convert fij + meta, layer1 -> B2[p]
// consumers (warps 4-7, 32f each): at meta-ready, cp.async hv slab; then
//                                  layer2 from B2[p]; epilogue reads hv smem
// named barriers: B2FULL=1,2  B2FREE=3,4  prod-internal=5  METAREADY=6,7
//
// dynamic smem (bytes):
//   B1    : 0      .. 9216    [e 64][g 64] f16 stride 144 (producer-private)
//   B2[2] : 9216   .. 44032   [e 64][f1 128] f16 stride 272, 17408 each
//   STG   : 44032  .. 53248   per consumer warp 2304B: [e 16][f 36] fp32
//   RAW[2]: 53248  .. 80384   13568 each (fij | rij | src | dst)
//   HV    : 80384  .. 113152  per consumer warp 8192B: [e 64][f 32] fp32
#define OFF_B2   9216
#define B2_SZ    17408
#define OFF_STG  44032
#define OFF_RAW  53248
#define RAW_SZ   13568
#define RAW_RIJ  12800
#define RAW_SRC  13056
#define RAW_DST  13312
#define OFF_HV   80384
#define SMEM_DYN 113152

__global__ void __launch_bounds__(256, 2) edge_kernel(
    const float* __restrict__ fij, const float* __restrict__ rij,
    const int* __restrict__ src, const int* __restrict__ dst,
    const float* __restrict__ Wf1, const float* __restrict__ bf1,
    const float* __restrict__ Wf2, const float* __restrict__ bf2) {
    extern __shared__ char sm[];
    char* pB1 = sm;

    __shared__ float C_s[2][ETILE];
    __shared__ int src_s[2][ETILE];
    __shared__ int dst_s[2][ETILE];

    const int tid  = threadIdx.x;
    const int wid  = tid >> 5;
    const int lane = tid & 31;
    const int grp  = lane >> 2;
    const int qid  = lane & 3;
    const int ec   = qid * 2;
    const int rr   = lane & 15;
    const int cc   = (lane >> 4) * 8;
    const int brow = (lane & 7) + ((lane >> 4) << 3);
    const int bko  = ((lane >> 3) & 1) * 16;
    const int G    = gridDim.x;
    const bool producer = (wid < 4);

    const uint32_t sBase = smem_u32(sm);
    const uint32_t sB1 = sBase;

    // ===== prologue: producers kick cp.async RAW[0] =====
    int tile0 = blockIdx.x;
    if (producer) {
        const float* fp = fij + (size_t)tile0 * (ETILE * NG);
#pragma unroll
        for (int i = 0; i < 7; i++) {
            int idx = tid + i * 128;
            if (idx < 800) cpasync16(sBase + OFF_RAW + idx * 16, fp + idx * 4);
        }
        if (tid < 16) {
            cpasync16(sBase + OFF_RAW + RAW_RIJ + tid * 16, rij + tile0 * ETILE + tid * 4);
            cpasync16(sBase + OFF_RAW + RAW_SRC + tid * 16, src + tile0 * ETILE + tid * 4);
            cpasync16(sBase + OFF_RAW + RAW_DST + tid * 16, dst + tile0 * ETILE + tid * 4);
        }
        CP_COMMIT();
    }

    // ===== setup: stage Wf2^T (str 272), consumers load a2h (64 regs) =====
    uint32_t a2h[64];
    for (int idx = tid; idx < 128 * 128; idx += 256) {
        int f1 = idx >> 7, f2 = idx & 127;
        *reinterpret_cast<uint16_t*>(sm + f2 * 272 + f1 * 2) = f16_hi(Wf2[idx]);
    }
    __syncthreads();
    if (!producer) {
        int f0c = (wid - 4) * 32;
#pragma unroll
        for (int mi = 0; mi < 2; mi++)
#pragma unroll
            for (int kc = 0; kc < 8; kc++)
                ldsm4(&a2h[mi * 32 + kc * 4],
                      sBase + (f0c + mi * 16 + rr) * 272 + (kc * 16 + cc) * 2);
    }
    __syncthreads();

    // ===== setup: stage Wf1^T (str 144, zero pad), producers load a1h =====
    {
        uint4* z = reinterpret_cast<uint4*>(sm);
        for (int i = tid; i < 18432 / 16; i += 256) z[i] = make_uint4(0, 0, 0, 0);
    }
    __syncthreads();
    for (int idx = tid; idx < NG * 128; idx += 256) {
        int g = idx >> 7, f = idx & 127;
        *reinterpret_cast<uint16_t*>(sm + f * 144 + g * 2) = f16_hi(Wf1[idx]);
    }
    __syncthreads();
    uint32_t a1h[32];
    if (producer) {
        int f0p = wid * 32;
#pragma unroll
        for (int mi = 0; mi < 2; mi++)
#pragma unroll
            for (int kc = 0; kc < 4; kc++)
                ldsm4(&a1h[mi * 16 + kc * 4],
                      sBase + (f0p + mi * 16 + rr) * 144 + (kc * 16 + cc) * 2);
    }
    __syncthreads();

    if (producer) {
        // ================= PRODUCER =================
        const int f0p = wid * 32;
        const uint32_t loff1 = (uint32_t)brow * 144 + bko;
        float b1a[2], b1b[2];
#pragma unroll
        for (int mi = 0; mi < 2; mi++) {
            b1a[mi] = bf1[f0p + mi * 16 + grp];
            b1b[mi] = bf1[f0p + mi * 16 + grp + 8];
        }
        int i = 0;
        for (int tile = blockIdx.x; tile < NTILES; tile += G, i++) {
            const int p = i & 1;
            char* pRAW = sm + OFF_RAW + p * RAW_SZ;
            char* pB2  = sm + OFF_B2 + p * B2_SZ;
            if (i >= 2) BAR_SYNC(3 + p, 256);  // B2[p], meta[p] free
            BAR_SYNC(5, 128);                   // B1 free
            CP_WAIT0();                          // RAW[p] loaded

            const int ptid = tid;  // 0..127
            for (int it = 0; it < 18; it++) {
                int idx = ptid + it * 128;
                int e = idx / 36, q = idx - e * 36;
                uint32_t w = 0u;
                if (q < 25) {
                    float2 v = *reinterpret_cast<const float2*>(pRAW + e * 200 + q * 8);
                    w = pack_h2(v.x, v.y);
                }
                *reinterpret_cast<uint32_t*>(pB1 + e * 144 + q * 4) = w;
            }
            if (ptid < ETILE) {
                float r = *reinterpret_cast<const float*>(pRAW + RAW_RIJ + ptid * 4);
                C_s[p][ptid] = (r < CUTOFF_R)
                    ? 0.5f * (__cosf(PI_F * r * (1.0f / CUTOFF_R)) + 1.0f) : 0.0f;
                src_s[p][ptid] = *reinterpret_cast<const int*>(pRAW + RAW_SRC + ptid * 4);
                dst_s[p][ptid] = *reinterpret_cast<const int*>(pRAW + RAW_DST + ptid * 4);
            }
            {
                int nt = tile + G;
                if (nt >= NTILES) nt = NTILES - 1;
                uint32_t sNR = sBase + OFF_RAW + (p ^ 1) * RAW_SZ;
                const float* np_ = fij + (size_t)nt * (ETILE * NG);
#pragma unroll
                for (int k = 0; k < 7; k++) {
                    int idx = ptid + k * 128;
                    if (idx < 800) cpasync16(sNR + idx * 16, np_ + idx * 4);
                }
                if (ptid < 16) {
                    cpasync16(sNR + RAW_RIJ + ptid * 16, rij + nt * ETILE + ptid * 4);
                    cpasync16(sNR + RAW_SRC + ptid * 16, src + nt * ETILE + ptid * 4);
                    cpasync16(sNR + RAW_DST + ptid * 16, dst + nt * ETILE + ptid * 4);
                }
                CP_COMMIT();
            }
            BAR_SYNC(5, 128);          // B1 + meta ready (producer-side)
            BAR_ARRIVE(6 + p, 256);    // signal consumers: meta[p] ready

            // layer 1: h1 = swish(Wf1^T @ fij^T + b1) -> B2[p]
#pragma unroll
            for (int np = 0; np < 4; np++) {
                float c0[2][4] = {{0,0,0,0},{0,0,0,0}};
                float c1[2][4] = {{0,0,0,0},{0,0,0,0}};
#pragma unroll
                for (int kc = 0; kc < 4; kc++) {
                    uint32_t bb[4];
                    ldsm4(bb, sB1 + np * (16 * 144) + kc * 32 + loff1);
                    mma16816(c0[0], &a1h[kc * 4],      &bb[0]);
                    mma16816(c1[0], &a1h[kc * 4],      &bb[2]);
                    mma16816(c0[1], &a1h[16 + kc * 4], &bb[0]);
                    mma16816(c1[1], &a1h[16 + kc * 4], &bb[2]);
                }
                int ea = np * 16 + ec, eb = ea + 8;
#pragma unroll
                for (int mi = 0; mi < 2; mi++) {
                    int f = f0p + mi * 16 + grp;
                    *reinterpret_cast<uint16_t*>(pB2 + ea * 272 + f * 2) =
                        f16_hi(swishf(c0[mi][0] + b1a[mi]));
                    *reinterpret_cast<uint16_t*>(pB2 + (ea + 1) * 272 + f * 2) =
                        f16_hi(swishf(c0[mi][1] + b1a[mi]));
                    *reinterpret_cast<uint16_t*>(pB2 + ea * 272 + (f + 8) * 2) =
                        f16_hi(swishf(c0[mi][2] + b1b[mi]));
                    *reinterpret_cast<uint16_t*>(pB2 + (ea + 1) * 272 + (f + 8) * 2) =
                        f16_hi(swishf(c0[mi][3] + b1b[mi]));
                    *reinterpret_cast<uint16_t*>(pB2 + eb * 272 + f * 2) =
                        f16_hi(swishf(c1[mi][0] + b1a[mi]));
                    *reinterpret_cast<uint16_t*>(pB2 + (eb + 1) * 272 + f * 2) =
                        f16_hi(swishf(c1[mi][1] + b1a[mi]));
                    *reinterpret_cast<uint16_t*>(pB2 + eb * 272 + (f + 8) * 2) =
                        f16_hi(swishf(c1[mi][2] + b1b[mi]));
                    *reinterpret_cast<uint16_t*>(pB2 + (eb + 1) * 272 + (f + 8) * 2) =
                        f16_hi(swishf(c1[mi][3] + b1b[mi]));
                }
            }
            BAR_ARRIVE(1 + p, 256);  // B2[p] full
        }
    } else {
        // ================= CONSUMER =================
        const int f0c = (wid - 4) * 32;
        const uint32_t loff2 = (uint32_t)brow * 272 + bko;
        float* stw = reinterpret_cast<float*>(sm + OFF_STG + (wid - 4) * 2304);
        char*  pHV = sm + OFF_HV + (wid - 4) * 8192;
        const uint32_t sHV = sBase + OFF_HV + (wid - 4) * 8192;
        float b2a[2], b2b[2];
#pragma unroll
        for (int mi = 0; mi < 2; mi++) {
            b2a[mi] = bf2[f0c + mi * 16 + grp];
            b2b[mi] = bf2[f0c + mi * 16 + grp + 8];
        }
        const int foL = (lane & 7) * 4;   // local f offset 0..28
        const int eb0 = lane >> 3;        // 0..3
        int i = 0;
        for (int tile = blockIdx.x; tile < NTILES; tile += G, i++) {
            const int p = i & 1;
            const uint32_t sB2p = sBase + OFF_B2 + p * B2_SZ;

            // ---- meta[p] ready: prefetch hv slab via cp.async ----
            BAR_SYNC(6 + p, 256);
#pragma unroll
            for (int it = 0; it < 16; it++) {
                int idx = lane + it * 32;
                int e = idx >> 3, c = idx & 7;
                cpasync16(sHV + e * 128 + c * 16,
                          &g_hv[(size_t)src_s[p][e] * NF + f0c + c * 4]);
            }
            CP_COMMIT();

            BAR_SYNC(1 + p, 256);  // B2[p] full

#pragma unroll
            for (int np = 0; np < 4; np++) {
                // layer-2 mma for np (16 edges)
                float c[2][2][4] = {{{0,0,0,0},{0,0,0,0}},{{0,0,0,0},{0,0,0,0}}};
#pragma unroll
                for (int kc = 0; kc < 8; kc++) {
                    uint32_t bb[4];
                    ldsm4(bb, sB2p + np * (16 * 272) + kc * 32 + loff2);
                    mma16816(c[0][0], &a2h[kc * 4],      &bb[0]);
                    mma16816(c[0][1], &a2h[kc * 4],      &bb[2]);
                    mma16816(c[1][0], &a2h[32 + kc * 4], &bb[0]);
                    mma16816(c[1][1], &a2h[32 + kc * 4], &bb[2]);
                }
                // stage warp-private 16e x 32f slab
#pragma unroll
                for (int mi = 0; mi < 2; mi++) {
                    int fL = mi * 16 + grp;
                    stw[ec * 36 + fL]           = c[mi][0][0] + b2a[mi];
                    stw[(ec + 1) * 36 + fL]     = c[mi][0][1] + b2a[mi];
                    stw[ec * 36 + fL + 8]       = c[mi][0][2] + b2b[mi];
                    stw[(ec + 1) * 36 + fL + 8] = c[mi][0][3] + b2b[mi];
                    stw[(ec + 8) * 36 + fL]     = c[mi][1][0] + b2a[mi];
                    stw[(ec + 9) * 36 + fL]     = c[mi][1][1] + b2a[mi];
                    stw[(ec + 8) * 36 + fL + 8] = c[mi][1][2] + b2b[mi];
                    stw[(ec + 9) * 36 + fL + 8] = c[mi][1][3] + b2b[mi];
                }
                if (np == 0) CP_WAIT0();  // hv slab landed (overlapped w/ mma)
                __syncwarp();

                // epilogue for np: hv from smem, red to gmem
#pragma unroll
                for (int j = 0; j < 4; j++) {
                    int eL = eb0 + j * 4;            // 0..15 local
                    int e  = np * 16 + eL;
                    float4 hv = *reinterpret_cast<const float4*>(
                        pHV + e * 128 + foL * 4);
                    float cv = C_s[p][e];
                    float* ag = &g_agg[(size_t)dst_s[p][e] * NF + f0c + foL];
                    float4 he = *reinterpret_cast<const float4*>(&stw[eL * 36 + foL]);
                    red4(ag, he.x * cv * hv.x, he.y * cv * hv.y,
                         he.z * cv * hv.z, he.w * cv * hv.w);
                }
                __syncwarp();
            }
            BAR_ARRIVE(3 + p, 256);  // B2[p], meta[p] free
        }
    }
}

// ---------------- launch ----------------
extern "C" void kernel_launch(void* const* d_in, const int* in_sizes, int n_in,
                              void* d_out, int out_size) {
    const float* feat   = (const float*)d_in[0];
    const float* fij    = (const float*)d_in[1];
    const float* rij    = (const float*)d_in[2];
    const int*   src    = (const int*)d_in[3];
    const int*   dst    = (const int*)d_in[4];
    const float* W_in2f = (const float*)d_in[5];
    const float* Wf1    = (const float*)d_in[6];
    const float* bf1    = (const float*)d_in[7];
    const float* Wf2    = (const float*)d_in[8];
    const float* bf2    = (const float*)d_in[9];
    const float* Wm1    = (const float*)d_in[10];
    const float* bm1    = (const float*)d_in[11];
    const float* Wm2    = (const float*)d_in[12];
    const float* bm2    = (const float*)d_in[13];
    float* out = (float*)d_out;

    static bool attr_done = false;
    if (!attr_done) {
        cudaFuncSetAttribute(edge_kernel,
                             cudaFuncAttributeMaxDynamicSharedMemorySize, SMEM_DYN);
        attr_done = true;
    }

    zero_agg_kernel<<<592, 256>>>();
    pad_kernel<<<1, 32>>>();
    k_hv<<<296, 256>>>(feat, W_in2f);
    edge_kernel<<<296, 256, SMEM_DYN>>>(fij, rij, src, dst, Wf1, bf1, Wf2, bf2);
    k_m1<<<296, 256>>>(Wm1, bm1);
    k_m2<<<296, 256>>>(Wm2, bm2, out);
}

// round 17
// speedup vs baseline: 1.0498x; 1.0498x over previous
#include <cuda_runtime.h>
#include <cuda_fp16.h>
#include <cstdint>

#define NNODES 50000
#define NEDGES 1600000
#define NF     128
#define NG     50
#define CUTOFF_R 5.0f
#define PI_F 3.14159265358979323846f

#define ETILE 64
#define NTILES (NEDGES / ETILE)   // 25000 exact

// ---------------- device scratch ----------------
__device__ float g_hv [NNODES * NF];
__device__ float g_agg[NNODES * NF];

// ---------------- helpers ----------------
__device__ __forceinline__ uint32_t smem_u32(const void* p) {
    uint32_t a;
    asm("{ .reg .u64 t; cvta.to.shared.u64 t, %1; cvt.u32.u64 %0, t; }"
        : "=r"(a) : "l"(p));
    return a;
}
__device__ __forceinline__ float swishf(float x) {
    return x * (1.0f / (1.0f + __expf(-x)));
}
__device__ __forceinline__ uint16_t f16_hi(float v) {
    __half h = __float2half_rn(v);
    return __half_raw(h).x;
}
__device__ __forceinline__ uint16_t f16_lo(float v) {
    __half h = __float2half_rn(v);
    float r = v - __half2float(h);
    __half l = __float2half_rn(r);
    return __half_raw(l).x;
}
__device__ __forceinline__ uint32_t pack_h2(float x, float y) {
    __half2 h = __floats2half2_rn(x, y);
    return *reinterpret_cast<uint32_t*>(&h);
}

__device__ __forceinline__ void ldsm4(uint32_t* r, uint32_t a) {
    asm volatile("ldmatrix.sync.aligned.m8n8.x4.shared.b16 {%0,%1,%2,%3}, [%4];"
                 : "=r"(r[0]), "=r"(r[1]), "=r"(r[2]), "=r"(r[3]) : "r"(a));
}
__device__ __forceinline__ void mma16816(float* c, const uint32_t* a, const uint32_t* b) {
    asm volatile(
        "mma.sync.aligned.m16n8k16.row.col.f32.f16.f16.f32 "
        "{%0,%1,%2,%3}, {%4,%5,%6,%7}, {%8,%9}, {%0,%1,%2,%3};"
        : "+f"(c[0]), "+f"(c[1]), "+f"(c[2]), "+f"(c[3])
        : "r"(a[0]), "r"(a[1]), "r"(a[2]), "r"(a[3]), "r"(b[0]), "r"(b[1]));
}
__device__ __forceinline__ void red4(float* p, float x, float y, float z, float w) {
    asm volatile("red.global.add.v4.f32 [%0], {%1,%2,%3,%4};"
                 :: "l"(p), "f"(x), "f"(y), "f"(z), "f"(w) : "memory");
}
__device__ __forceinline__ void cpasync16(uint32_t s, const void* g) {
    asm volatile("cp.async.cg.shared.global [%0], [%1], 16;" :: "r"(s), "l"(g));
}
#define CP_COMMIT() asm volatile("cp.async.commit_group;" ::: "memory")
#define CP_WAIT0()  asm volatile("cp.async.wait_group 0;" ::: "memory")
#define BAR_SYNC(id, cnt) \
    asm volatile("bar.sync %0, %1;" :: "r"(id), "r"(cnt) : "memory")
#define BAR_ARRIVE(id, cnt) \
    asm volatile("bar.arrive %0, %1;" :: "r"(id), "r"(cnt) : "memory")

// ---------------- HMMA node GEMM body (from R12, proven) ----------------
template <bool SWISH, bool HAS_BIAS>
__device__ __forceinline__ void gemm_hmma(const float* __restrict__ in,
                                          const float* __restrict__ W,
                                          const float* __restrict__ bias,
                                          float* __restrict__ out, int nrows) {
    __shared__ __align__(16) char nsm[34816];
    const int tid  = threadIdx.x;
    const int wid  = tid >> 5;
    const int lane = tid & 31;
    const int f0   = wid * 16;
    const int grp  = lane >> 2;
    const int qid  = lane & 3;
    const int f_r  = f0 + grp;
    const int ec   = qid * 2;
    const int rr   = lane & 15;
    const int cc   = (lane >> 4) * 8;
    const int brow = (lane & 7) + ((lane >> 4) << 3);
    const int bko  = ((lane >> 3) & 1) * 16;
    const uint32_t loff = (uint32_t)brow * 272 + bko;
    const uint32_t sN = smem_u32(nsm);
    const int G = gridDim.x;

    uint32_t awh[32], awl[32];
    for (int idx = tid; idx < 128 * 128; idx += 256) {
        int j = idx & 127, k = idx >> 7;
        *reinterpret_cast<uint16_t*>(nsm + j * 272 + k * 2) = f16_hi(W[k * 128 + j]);
    }
    __syncthreads();
#pragma unroll
    for (int kc = 0; kc < 8; kc++)
        ldsm4(&awh[kc * 4], sN + (f0 + rr) * 272 + (kc * 16 + cc) * 2);
    __syncthreads();
    for (int idx = tid; idx < 128 * 128; idx += 256) {
        int j = idx & 127, k = idx >> 7;
        *reinterpret_cast<uint16_t*>(nsm + j * 272 + k * 2) = f16_lo(W[k * 128 + j]);
    }
    __syncthreads();
#pragma unroll
    for (int kc = 0; kc < 8; kc++)
        ldsm4(&awl[kc * 4], sN + (f0 + rr) * 272 + (kc * 16 + cc) * 2);
    __syncthreads();

    const float ba  = HAS_BIAS ? bias[f_r] : 0.0f;
    const float bb_ = HAS_BIAS ? bias[f_r + 8] : 0.0f;

    const int NT = (nrows + 63) >> 6;
    for (int tile = blockIdx.x; tile < NT; tile += G) {
        for (int idx = tid; idx < 4096; idx += 256) {
            int r = idx >> 6, q = idx & 63;
            int rg = tile * 64 + r;
            int rc = rg < nrows ? rg : 0;
            float2 v = *reinterpret_cast<const float2*>(in + (size_t)rc * 128 + q * 2);
            *reinterpret_cast<uint32_t*>(nsm + r * 272 + q * 4) = pack_h2(v.x, v.y);
        }
        __syncthreads();

#pragma unroll
        for (int np = 0; np < 4; np++) {
            float c0h[4] = {0,0,0,0}, c0l[4] = {0,0,0,0};
            float c1h[4] = {0,0,0,0}, c1l[4] = {0,0,0,0};
#pragma unroll
            for (int kc = 0; kc < 8; kc++) {
                uint32_t bb[4];
                ldsm4(bb, sN + np * (16 * 272) + kc * 32 + loff);
                mma16816(c0h, &awh[kc * 4], &bb[0]);
                mma16816(c0l, &awl[kc * 4], &bb[0]);
                mma16816(c1h, &awh[kc * 4], &bb[2]);
                mma16816(c1l, &awl[kc * 4], &bb[2]);
            }
            int ra = tile * 64 + np * 16 + ec;
            int rb = ra + 8;
            float v;
            if (ra < nrows) {
                v = c0h[0] + c0l[0] + ba; if (SWISH) v = swishf(v);
                out[(size_t)ra * 128 + f_r] = v;
                v = c0h[2] + c0l[2] + bb_; if (SWISH) v = swishf(v);
                out[(size_t)ra * 128 + f_r + 8] = v;
            }
            if (ra + 1 < nrows) {
                v = c0h[1] + c0l[1] + ba; if (SWISH) v = swishf(v);
                out[(size_t)(ra + 1) * 128 + f_r] = v;
                v = c0h[3] + c0l[3] + bb_; if (SWISH) v = swishf(v);
                out[(size_t)(ra + 1) * 128 + f_r + 8] = v;
            }
            if (rb < nrows) {
                v = c1h[0] + c1l[0] + ba; if (SWISH) v = swishf(v);
                out[(size_t)rb * 128 + f_r] = v;
                v = c1h[2] + c1l[2] + bb_; if (SWISH) v = swishf(v);
                out[(size_t)rb * 128 + f_r + 8] = v;
            }
            if (rb + 1 < nrows) {
                v = c1h[1] + c1l[1] + ba; if (SWISH) v = swishf(v);
                out[(size_t)(rb + 1) * 128 + f_r] = v;
                v = c1h[3] + c1l[3] + bb_; if (SWISH) v = swishf(v);
                out[(size_t)(rb + 1) * 128 + f_r + 8] = v;
            }
        }
        __syncthreads();
    }
}

// k_hv: zero g_agg, then hv = feat @ W_in2f
__global__ void __launch_bounds__(256, 2) k_hv(const float* __restrict__ feat,
                                               const float* __restrict__ W_in2f) {
    float4* p = reinterpret_cast<float4*>(g_agg);
    int n4 = NNODES * NF / 4;
    for (int i = blockIdx.x * blockDim.x + threadIdx.x; i < n4;
         i += gridDim.x * blockDim.x)
        p[i] = make_float4(0.f, 0.f, 0.f, 0.f);
    gemm_hmma<false, false>(feat, W_in2f, nullptr, g_hv, NNODES);
}

// ---------------- fused msg_transform: out = (swish(agg@W1+b1))@W2 + b2 ----
// GEMM1: W1 as fp16 hi+lo (awh1/awl1), GEMM2: W2 single fp16 (awh2).
// smem: setup staging 0..34816; runtime Bin 0..17408, h 17408..34816.
__global__ void __launch_bounds__(256, 2) k_mlp(const float* __restrict__ Wm1,
                                                const float* __restrict__ bm1,
                                                const float* __restrict__ Wm2,
                                                const float* __restrict__ bm2,
                                                float* __restrict__ out) {
    __shared__ __align__(16) char nsm[34816];
    const int tid  = threadIdx.x;
    const int wid  = tid >> 5;
    const int lane = tid & 31;
    const int f0   = wid * 16;
    const int grp  = lane >> 2;
    const int qid  = lane & 3;
    const int f_r  = f0 + grp;
    const int ec   = qid * 2;
    const int rr   = lane & 15;
    const int cc   = (lane >> 4) * 8;
    const int brow = (lane & 7) + ((lane >> 4) << 3);
    const int bko  = ((lane >> 3) & 1) * 16;
    const uint32_t loff = (uint32_t)brow * 272 + bko;
    const uint32_t sN = smem_u32(nsm);
    const uint32_t sH = sN + 17408;
    char* pH = nsm + 17408;
    const int G = gridDim.x;

    // setup: W1 hi, W1 lo, W2 hi fragments
    uint32_t awh1[32], awl1[32], awh2[32];
    for (int idx = tid; idx < 128 * 128; idx += 256) {
        int j = idx & 127, k = idx >> 7;
        *reinterpret_cast<uint16_t*>(nsm + j * 272 + k * 2) = f16_hi(Wm1[k * 128 + j]);
    }
    __syncthreads();
#pragma unroll
    for (int kc = 0; kc < 8; kc++)
        ldsm4(&awh1[kc * 4], sN + (f0 + rr) * 272 + (kc * 16 + cc) * 2);
    __syncthreads();
    for (int idx = tid; idx < 128 * 128; idx += 256) {
        int j = idx & 127, k = idx >> 7;
        *reinterpret_cast<uint16_t*>(nsm + j * 272 + k * 2) = f16_lo(Wm1[k * 128 + j]);
    }
    __syncthreads();
#pragma unroll
    for (int kc = 0; kc < 8; kc++)
        ldsm4(&awl1[kc * 4], sN + (f0 + rr) * 272 + (kc * 16 + cc) * 2);
    __syncthreads();
    for (int idx = tid; idx < 128 * 128; idx += 256) {
        int j = idx & 127, k = idx >> 7;
        *reinterpret_cast<uint16_t*>(nsm + j * 272 + k * 2) = f16_hi(Wm2[k * 128 + j]);
    }
    __syncthreads();
#pragma unroll
    for (int kc = 0; kc < 8; kc++)
        ldsm4(&awh2[kc * 4], sN + (f0 + rr) * 272 + (kc * 16 + cc) * 2);
    __syncthreads();

    const float b1a = bm1[f_r], b1b = bm1[f_r + 8];
    const float b2a = bm2[f_r], b2b = bm2[f_r + 8];

    const int NT = (NNODES + 63) >> 6;  // 782
    for (int tile = blockIdx.x; tile < NT; tile += G) {
        // convert agg rows -> f16 Bin [r 64][k 128] stride 272
        for (int idx = tid; idx < 4096; idx += 256) {
            int r = idx >> 6, q = idx & 63;
            int rg = tile * 64 + r;
            int rc = rg < NNODES ? rg : 0;
            float2 v = *reinterpret_cast<const float2*>(g_agg + (size_t)rc * 128 + q * 2);
            *reinterpret_cast<uint32_t*>(nsm + r * 272 + q * 4) = pack_h2(v.x, v.y);
        }
        __syncthreads();

        // GEMM1 + swish -> h (f16, [r 64][f1 128] stride 272)
#pragma unroll
        for (int np = 0; np < 4; np++) {
            float c0h[4] = {0,0,0,0}, c0l[4] = {0,0,0,0};
            float c1h[4] = {0,0,0,0}, c1l[4] = {0,0,0,0};
#pragma unroll
            for (int kc = 0; kc < 8; kc++) {
                uint32_t bb[4];
                ldsm4(bb, sN + np * (16 * 272) + kc * 32 + loff);
                mma16816(c0h, &awh1[kc * 4], &bb[0]);
                mma16816(c0l, &awl1[kc * 4], &bb[0]);
                mma16816(c1h, &awh1[kc * 4], &bb[2]);
                mma16816(c1l, &awl1[kc * 4], &bb[2]);
            }
            int la = np * 16 + ec, lb = la + 8;
            *reinterpret_cast<uint16_t*>(pH + la * 272 + f_r * 2) =
                f16_hi(swishf(c0h[0] + c0l[0] + b1a));
            *reinterpret_cast<uint16_t*>(pH + (la + 1) * 272 + f_r * 2) =
                f16_hi(swishf(c0h[1] + c0l[1] + b1a));
            *reinterpret_cast<uint16_t*>(pH + la * 272 + (f_r + 8) * 2) =
                f16_hi(swishf(c0h[2] + c0l[2] + b1b));
            *reinterpret_cast<uint16_t*>(pH + (la + 1) * 272 + (f_r + 8) * 2) =
                f16_hi(swishf(c0h[3] + c0l[3] + b1b));
            *reinterpret_cast<uint16_t*>(pH + lb * 272 + f_r * 2) =
                f16_hi(swishf(c1h[0] + c1l[0] + b1a));
            *reinterpret_cast<uint16_t*>(pH + (lb + 1) * 272 + f_r * 2) =
                f16_hi(swishf(c1h[1] + c1l[1] + b1a));
            *reinterpret_cast<uint16_t*>(pH + lb * 272 + (f_r + 8) * 2) =
                f16_hi(swishf(c1h[2] + c1l[2] + b1b));
            *reinterpret_cast<uint16_t*>(pH + (lb + 1) * 272 + (f_r + 8) * 2) =
                f16_hi(swishf(c1h[3] + c1l[3] + b1b));
        }
        __syncthreads();

        // GEMM2 -> out (fp32 global)
#pragma unroll
        for (int np = 0; np < 4; np++) {
            float c0[4] = {0,0,0,0}, c1[4] = {0,0,0,0};
#pragma unroll
            for (int kc = 0; kc < 8; kc++) {
                uint32_t bb[4];
                ldsm4(bb, sH + np * (16 * 272) + kc * 32 + loff);
                mma16816(c0, &awh2[kc * 4], &bb[0]);
                mma16816(c1, &awh2[kc * 4], &bb[2]);
            }
            int ra = tile * 64 + np * 16 + ec;
            int rb = ra + 8;
            if (ra < NNODES) {
                out[(size_t)ra * 128 + f_r]     = c0[0] + b2a;
                out[(size_t)ra * 128 + f_r + 8] = c0[2] + b2b;
            }
            if (ra + 1 < NNODES) {
                out[(size_t)(ra + 1) * 128 + f_r]     = c0[1] + b2a;
                out[(size_t)(ra + 1) * 128 + f_r + 8] = c0[3] + b2b;
            }
            if (rb < NNODES) {
                out[(size_t)rb * 128 + f_r]     = c1[0] + b2a;
                out[(size_t)rb * 128 + f_r + 8] = c1[2] + b2b;
            }
            if (rb + 1 < NNODES) {
                out[(size_t)(rb + 1) * 128 + f_r]     = c1[1] + b2a;
                out[(size_t)(rb + 1) * 128 + f_r + 8] = c1[3] + b2b;
            }
        }
        __syncthreads();
    }
}

// ---------------- warp-specialized HMMA edge kernel (R14, verbatim) --------
#define OFF_B2   9216
#define B2_SZ    17408
#define OFF_STG  44032
#define OFF_RAW  77824
#define RAW_SZ   13568
#define RAW_RIJ  12800
#define RAW_SRC  13056
#define RAW_DST  13312
#define SMEM_DYN 104960

__global__ void __launch_bounds__(256, 2) edge_kernel(
    const float* __restrict__ fij, const float* __restrict__ rij,
    const int* __restrict__ src, const int* __restrict__ dst,
    const float* __restrict__ Wf1, const float* __restrict__ bf1,
    const float* __restrict__ Wf2, const float* __restrict__ bf2) {
    extern __shared__ char sm[];
    char* pB1 = sm;
    float* stage = reinterpret_cast<float*>(sm + OFF_STG);

    __shared__ float C_s[2][ETILE];
    __shared__ int src_s[2][ETILE];
    __shared__ int dst_s[2][ETILE];

    const int tid  = threadIdx.x;
    const int wid  = tid >> 5;
    const int lane = tid & 31;
    const int grp  = lane >> 2;
    const int qid  = lane & 3;
    const int ec   = qid * 2;
    const int rr   = lane & 15;
    const int cc   = (lane >> 4) * 8;
    const int brow = (lane & 7) + ((lane >> 4) << 3);
    const int bko  = ((lane >> 3) & 1) * 16;
    const int G    = gridDim.x;
    const bool producer = (wid < 4);

    const uint32_t sBase = smem_u32(sm);
    const uint32_t sB1 = sBase;

    int tile0 = blockIdx.x;
    if (producer) {
        const float* fp = fij + (size_t)tile0 * (ETILE * NG);
#pragma unroll
        for (int i = 0; i < 7; i++) {
            int idx = tid + i * 128;
            if (idx < 800) cpasync16(sBase + OFF_RAW + idx * 16, fp + idx * 4);
        }
        if (tid < 16) {
            cpasync16(sBase + OFF_RAW + RAW_RIJ + tid * 16, rij + tile0 * ETILE + tid * 4);
            cpasync16(sBase + OFF_RAW + RAW_SRC + tid * 16, src + tile0 * ETILE + tid * 4);
            cpasync16(sBase + OFF_RAW + RAW_DST + tid * 16, dst + tile0 * ETILE + tid * 4);
        }
        CP_COMMIT();
    }

    uint32_t a2h[64];
    for (int idx = tid; idx < 128 * 128; idx += 256) {
        int f1 = idx >> 7, f2 = idx & 127;
        *reinterpret_cast<uint16_t*>(sm + f2 * 272 + f1 * 2) = f16_hi(Wf2[idx]);
    }
    __syncthreads();
    if (!producer) {
        int f0c = (wid - 4) * 32;
#pragma unroll
        for (int mi = 0; mi < 2; mi++)
#pragma unroll
            for (int kc = 0; kc < 8; kc++)
                ldsm4(&a2h[mi * 32 + kc * 4],
                      sBase + (f0c + mi * 16 + rr) * 272 + (kc * 16 + cc) * 2);
    }
    __syncthreads();

    {
        uint4* z = reinterpret_cast<uint4*>(sm);
        for (int i = tid; i < 18432 / 16; i += 256) z[i] = make_uint4(0, 0, 0, 0);
    }
    __syncthreads();
    for (int idx = tid; idx < NG * 128; idx += 256) {
        int g = idx >> 7, f = idx & 127;
        *reinterpret_cast<uint16_t*>(sm + f * 144 + g * 2) = f16_hi(Wf1[idx]);
    }
    __syncthreads();
    uint32_t a1h[32];
    if (producer) {
        int f0p = wid * 32;
#pragma unroll
        for (int mi = 0; mi < 2; mi++)
#pragma unroll
            for (int kc = 0; kc < 4; kc++)
                ldsm4(&a1h[mi * 16 + kc * 4],
                      sBase + (f0p + mi * 16 + rr) * 144 + (kc * 16 + cc) * 2);
    }
    __syncthreads();

    if (producer) {
        const int f0p = wid * 32;
        const uint32_t loff1 = (uint32_t)brow * 144 + bko;
        float b1a[2], b1b[2];
#pragma unroll
        for (int mi = 0; mi < 2; mi++) {
            b1a[mi] = bf1[f0p + mi * 16 + grp];
            b1b[mi] = bf1[f0p + mi * 16 + grp + 8];
        }
        int i = 0;
        for (int tile = blockIdx.x; tile < NTILES; tile += G, i++) {
            const int p = i & 1;
            char* pRAW = sm + OFF_RAW + p * RAW_SZ;
            char* pB2  = sm + OFF_B2 + p * B2_SZ;
            if (i >= 2) BAR_SYNC(3 + p, 256);
            BAR_SYNC(5, 128);
            CP_WAIT0();

            const int ptid = tid;
            for (int it = 0; it < 18; it++) {
                int idx = ptid + it * 128;
                int e = idx / 36, q = idx - e * 36;
                uint32_t w = 0u;
                if (q < 25) {
                    float2 v = *reinterpret_cast<const float2*>(pRAW + e * 200 + q * 8);
                    w = pack_h2(v.x, v.y);
                }
                *reinterpret_cast<uint32_t*>(pB1 + e * 144 + q * 4) = w;
            }
            if (ptid < ETILE) {
                float r = *reinterpret_cast<const float*>(pRAW + RAW_RIJ + ptid * 4);
                C_s[p][ptid] = (r < CUTOFF_R)
                    ? 0.5f * (__cosf(PI_F * r * (1.0f / CUTOFF_R)) + 1.0f) : 0.0f;
                src_s[p][ptid] = *reinterpret_cast<const int*>(pRAW + RAW_SRC + ptid * 4);
                dst_s[p][ptid] = *reinterpret_cast<const int*>(pRAW + RAW_DST + ptid * 4);
            }
            {
                int nt = tile + G;
                if (nt >= NTILES) nt = NTILES - 1;
                uint32_t sNR = sBase + OFF_RAW + (p ^ 1) * RAW_SZ;
                const float* np_ = fij + (size_t)nt * (ETILE * NG);
#pragma unroll
                for (int k = 0; k < 7; k++) {
                    int idx = ptid + k * 128;
                    if (idx < 800) cpasync16(sNR + idx * 16, np_ + idx * 4);
                }
                if (ptid < 16) {
                    cpasync16(sNR + RAW_RIJ + ptid * 16, rij + nt * ETILE + ptid * 4);
                    cpasync16(sNR + RAW_SRC + ptid * 16, src + nt * ETILE + ptid * 4);
                    cpasync16(sNR + RAW_DST + ptid * 16, dst + nt * ETILE + ptid * 4);
                }
                CP_COMMIT();
            }
            BAR_SYNC(5, 128);

#pragma unroll
            for (int np = 0; np < 4; np++) {
                float c0[2][4] = {{0,0,0,0},{0,0,0,0}};
                float c1[2][4] = {{0,0,0,0},{0,0,0,0}};
#pragma unroll
                for (int kc = 0; kc < 4; kc++) {
                    uint32_t bb[4];
                    ldsm4(bb, sB1 + np * (16 * 144) + kc * 32 + loff1);
                    mma16816(c0[0], &a1h[kc * 4],      &bb[0]);
                    mma16816(c1[0], &a1h[kc * 4],      &bb[2]);
                    mma16816(c0[1], &a1h[16 + kc * 4], &bb[0]);
                    mma16816(c1[1], &a1h[16 + kc * 4], &bb[2]);
                }
                int ea = np * 16 + ec, eb = ea + 8;
#pragma unroll
                for (int mi = 0; mi < 2; mi++) {
                    int f = f0p + mi * 16 + grp;
                    *reinterpret_cast<uint16_t*>(pB2 + ea * 272 + f * 2) =
                        f16_hi(swishf(c0[mi][0] + b1a[mi]));
                    *reinterpret_cast<uint16_t*>(pB2 + (ea + 1) * 272 + f * 2) =
                        f16_hi(swishf(c0[mi][1] + b1a[mi]));
                    *reinterpret_cast<uint16_t*>(pB2 + ea * 272 + (f + 8) * 2) =
                        f16_hi(swishf(c0[mi][2] + b1b[mi]));
                    *reinterpret_cast<uint16_t*>(pB2 + (ea + 1) * 272 + (f + 8) * 2) =
                        f16_hi(swishf(c0[mi][3] + b1b[mi]));
                    *reinterpret_cast<uint16_t*>(pB2 + eb * 272 + f * 2) =
                        f16_hi(swishf(c1[mi][0] + b1a[mi]));
                    *reinterpret_cast<uint16_t*>(pB2 + (eb + 1) * 272 + f * 2) =
                        f16_hi(swishf(c1[mi][1] + b1a[mi]));
                    *reinterpret_cast<uint16_t*>(pB2 + eb * 272 + (f + 8) * 2) =
                        f16_hi(swishf(c1[mi][2] + b1b[mi]));
                    *reinterpret_cast<uint16_t*>(pB2 + (eb + 1) * 272 + (f + 8) * 2) =
                        f16_hi(swishf(c1[mi][3] + b1b[mi]));
                }
            }
            BAR_ARRIVE(1 + p, 256);
        }
    } else {
        const int f0c = (wid - 4) * 32;
        const uint32_t loff2 = (uint32_t)brow * 272 + bko;
        float b2a[2], b2b[2];
#pragma unroll
        for (int mi = 0; mi < 2; mi++) {
            b2a[mi] = bf2[f0c + mi * 16 + grp];
            b2b[mi] = bf2[f0c + mi * 16 + grp + 8];
        }
        const int fo  = f0c + (lane & 7) * 4;
        const int eb0 = lane >> 3;
        int i = 0;
        for (int tile = blockIdx.x; tile < NTILES; tile += G, i++) {
            const int p = i & 1;
            const uint32_t sB2p = sBase + OFF_B2 + p * B2_SZ;
            BAR_SYNC(1 + p, 256);

#pragma unroll
            for (int np = 0; np < 4; np++) {
                float c[2][2][4] = {{{0,0,0,0},{0,0,0,0}},{{0,0,0,0},{0,0,0,0}}};
#pragma unroll
                for (int kc = 0; kc < 8; kc++) {
                    uint32_t bb[4];
                    ldsm4(bb, sB2p + np * (16 * 272) + kc * 32 + loff2);
                    mma16816(c[0][0], &a2h[kc * 4],      &bb[0]);
                    mma16816(c[0][1], &a2h[kc * 4],      &bb[2]);
                    mma16816(c[1][0], &a2h[32 + kc * 4], &bb[0]);
                    mma16816(c[1][1], &a2h[32 + kc * 4], &bb[2]);
                }
                int ea = np * 16 + ec, eb = ea + 8;
#pragma unroll
                for (int mi = 0; mi < 2; mi++) {
                    int f = f0c + mi * 16 + grp;
                    stage[ea * 132 + f]           = c[mi][0][0] + b2a[mi];
                    stage[(ea + 1) * 132 + f]     = c[mi][0][1] + b2a[mi];
                    stage[ea * 132 + f + 8]       = c[mi][0][2] + b2b[mi];
                    stage[(ea + 1) * 132 + f + 8] = c[mi][0][3] + b2b[mi];
                    stage[eb * 132 + f]           = c[mi][1][0] + b2a[mi];
                    stage[(eb + 1) * 132 + f]     = c[mi][1][1] + b2a[mi];
                    stage[eb * 132 + f + 8]       = c[mi][1][2] + b2b[mi];
                    stage[(eb + 1) * 132 + f + 8] = c[mi][1][3] + b2b[mi];
                }
            }
            __syncwarp();

#pragma unroll
            for (int h = 0; h < 4; h++) {
                float4 hv[4], st4[4];
                float cv[4];
                float* ag[4];
#pragma unroll
                for (int j = 0; j < 4; j++) {
                    int e = (h * 4 + j) * 4 + eb0;
                    hv[j] = __ldg(reinterpret_cast<const float4*>(
                        &g_hv[(size_t)src_s[p][e] * NF + fo]));
                    st4[j] = *reinterpret_cast<const float4*>(&stage[e * 132 + fo]);
                    cv[j] = C_s[p][e];
                    ag[j] = &g_agg[(size_t)dst_s[p][e] * NF + fo];
                }
#pragma unroll
                for (int j = 0; j < 4; j++) {
                    red4(ag[j], st4[j].x * cv[j] * hv[j].x,
                         st4[j].y * cv[j] * hv[j].y,
                         st4[j].z * cv[j] * hv[j].z,
                         st4[j].w * cv[j] * hv[j].w);
                }
            }
            __syncwarp();
            BAR_ARRIVE(3 + p, 256);
        }
    }
}

// ---------------- launch ----------------
extern "C" void kernel_launch(void* const* d_in, const int* in_sizes, int n_in,
                              void* d_out, int out_size) {
    const float* feat   = (const float*)d_in[0];
    const float* fij    = (const float*)d_in[1];
    const float* rij    = (const float*)d_in[2];
    const int*   src    = (const int*)d_in[3];
    const int*   dst    = (const int*)d_in[4];
    const float* W_in2f = (const float*)d_in[5];
    const float* Wf1    = (const float*)d_in[6];
    const float* bf1    = (const float*)d_in[7];
    const float* Wf2    = (const float*)d_in[8];
    const float* bf2    = (const float*)d_in[9];
    const float* Wm1    = (const float*)d_in[10];
    const float* bm1    = (const float*)d_in[11];
    const float* Wm2    = (const float*)d_in[12];
    const float* bm2    = (const float*)d_in[13];
    float* out = (float*)d_out;

    static bool attr_done = false;
    if (!attr_done) {
        cudaFuncSetAttribute(edge_kernel,
                             cudaFuncAttributeMaxDynamicSharedMemorySize, SMEM_DYN);
        attr_done = true;
    }

    k_hv<<<296, 256>>>(feat, W_in2f);
    edge_kernel<<<296, 256, SMEM_DYN>>>(fij, rij, src, dst, Wf1, bf1, Wf2, bf2);
    k_mlp<<<296, 256>>>(Wm1, bm1, Wm2, bm2, out);
}